// round 2
// baseline (speedup 1.0000x reference)
#include <cuda_runtime.h>
#include <math.h>

// ---------------- problem constants ----------------
#define BATCH  16384
#define SDIM   128
#define ENCK   10
#define KIN    1280      // SDIM*ENCK
#define H0     2048
#define H1     2048
#define ADIM   32
#define DECK   10
#define NOUT   320       // ADIM*DECK

// ---------------- scratch (device globals; no allocation allowed) ----------
__device__ float g_spine[(size_t)BATCH * KIN];
__device__ float g_a1[(size_t)BATCH * H0];
__device__ float g_a2[(size_t)BATCH * H1];
__device__ float g_a3[(size_t)BATCH * NOUT];

// ---------------- encoder: spine = sigmoid((state - mean)/std) -------------
__global__ void encoder_kernel(const float* __restrict__ state,
                               const float* __restrict__ mean,
                               const float* __restrict__ stdv,
                               float* __restrict__ spine)
{
    int i = blockIdx.x * blockDim.x + threadIdx.x;
    const int total = BATCH * KIN;
    if (i >= total) return;
    int b = i / KIN;
    int k = i - b * KIN;
    int d = k / ENCK;
    float x = (state[b * SDIM + d] - mean[k]) / stdv[k];
    spine[i] = 1.0f / (1.0f + __expf(-x));
}

// ---------------- tiled TN GEMM: C[M,N] = A[M,K] * W[N,K]^T + bias ---------
// BM=128, BN=128, BK=16, 256 threads, 8x8 per-thread microtile.
// Double-buffered smem with register staging: one barrier per K-step.
// Warp layout: 8 warps as 4(m) x 2(n); lanes 4(m) x 8(n) -> conflict-free LDS.
// M, K multiples of 128/16; N may be ragged (GEMM3: N=320) -> guarded.
template <int RELU>
__global__ void __launch_bounds__(256, 2)
gemm_tn(const float* __restrict__ A,
        const float* __restrict__ W,
        const float* __restrict__ bias,
        float* __restrict__ C,
        int M, int N, int K)
{
    const int BM = 128, BN = 128, BK = 16;
    __shared__ float As[2][BK][BM];
    __shared__ float Bs[2][BK][BN];

    int tid = threadIdx.x;
    int bm = blockIdx.y * BM;
    int bn = blockIdx.x * BN;

    int w = tid >> 5, l = tid & 31;
    int tm = ((w >> 1) << 5) + ((l >> 3) << 3);  // warp_m*32 + lane_m*8
    int tn = ((w & 1) << 6) + ((l & 7) << 3);    // warp_n*64 + lane_n*8

    // gmem tile loading: 128 rows x 16 cols per operand; each thread: 2x float4
    int lrow = tid >> 2;          // 0..63
    int lcol = (tid & 3) << 2;    // 0,4,8,12

    float acc[8][8];
#pragma unroll
    for (int i = 0; i < 8; i++)
#pragma unroll
        for (int j = 0; j < 8; j++) acc[i][j] = 0.0f;

    const float* Ap0 = A + (size_t)(bm + lrow) * K + lcol;
    const float* Ap1 = Ap0 + (size_t)64 * K;
    int n0 = bn + lrow;
    int n1 = bn + lrow + 64;
    const float* Wp0 = W + (size_t)n0 * K + lcol;
    const float* Wp1 = W + (size_t)n1 * K + lcol;
    bool okn0 = (n0 < N), okn1 = (n1 < N);

    // ---- prologue: load tile 0 into buffer 0 ----
    {
        float4 av0 = *(const float4*)(Ap0);
        float4 av1 = *(const float4*)(Ap1);
        float4 bv0 = okn0 ? *(const float4*)(Wp0) : make_float4(0.f, 0.f, 0.f, 0.f);
        float4 bv1 = okn1 ? *(const float4*)(Wp1) : make_float4(0.f, 0.f, 0.f, 0.f);
        As[0][lcol + 0][lrow] = av0.x;  As[0][lcol + 1][lrow] = av0.y;
        As[0][lcol + 2][lrow] = av0.z;  As[0][lcol + 3][lrow] = av0.w;
        As[0][lcol + 0][lrow + 64] = av1.x;  As[0][lcol + 1][lrow + 64] = av1.y;
        As[0][lcol + 2][lrow + 64] = av1.z;  As[0][lcol + 3][lrow + 64] = av1.w;
        Bs[0][lcol + 0][lrow] = bv0.x;  Bs[0][lcol + 1][lrow] = bv0.y;
        Bs[0][lcol + 2][lrow] = bv0.z;  Bs[0][lcol + 3][lrow] = bv0.w;
        Bs[0][lcol + 0][lrow + 64] = bv1.x;  Bs[0][lcol + 1][lrow + 64] = bv1.y;
        Bs[0][lcol + 2][lrow + 64] = bv1.z;  Bs[0][lcol + 3][lrow + 64] = bv1.w;
    }
    __syncthreads();

    int nsteps = K / BK;
    for (int s = 0; s < nsteps; s++) {
        int cur = s & 1;
        int nxt = cur ^ 1;
        int knext = (s + 1) * BK;
        bool has_next = (knext < K);

        // issue next tile's global loads early (latency hidden by compute)
        float4 av0, av1, bv0, bv1;
        if (has_next) {
            av0 = *(const float4*)(Ap0 + knext);
            av1 = *(const float4*)(Ap1 + knext);
            bv0 = okn0 ? *(const float4*)(Wp0 + knext) : make_float4(0.f, 0.f, 0.f, 0.f);
            bv1 = okn1 ? *(const float4*)(Wp1 + knext) : make_float4(0.f, 0.f, 0.f, 0.f);
        }

        // compute on current buffer
#pragma unroll
        for (int kk = 0; kk < BK; kk++) {
            float4 af0 = *(const float4*)&As[cur][kk][tm];
            float4 af1 = *(const float4*)&As[cur][kk][tm + 4];
            float4 bf0 = *(const float4*)&Bs[cur][kk][tn];
            float4 bf1 = *(const float4*)&Bs[cur][kk][tn + 4];
            float afr[8] = {af0.x, af0.y, af0.z, af0.w, af1.x, af1.y, af1.z, af1.w};
            float bfr[8] = {bf0.x, bf0.y, bf0.z, bf0.w, bf1.x, bf1.y, bf1.z, bf1.w};
#pragma unroll
            for (int i = 0; i < 8; i++)
#pragma unroll
                for (int j = 0; j < 8; j++)
                    acc[i][j] = fmaf(afr[i], bfr[j], acc[i][j]);
        }

        // store next tile into the other buffer, single barrier per step
        if (has_next) {
            As[nxt][lcol + 0][lrow] = av0.x;  As[nxt][lcol + 1][lrow] = av0.y;
            As[nxt][lcol + 2][lrow] = av0.z;  As[nxt][lcol + 3][lrow] = av0.w;
            As[nxt][lcol + 0][lrow + 64] = av1.x;  As[nxt][lcol + 1][lrow + 64] = av1.y;
            As[nxt][lcol + 2][lrow + 64] = av1.z;  As[nxt][lcol + 3][lrow + 64] = av1.w;
            Bs[nxt][lcol + 0][lrow] = bv0.x;  Bs[nxt][lcol + 1][lrow] = bv0.y;
            Bs[nxt][lcol + 2][lrow] = bv0.z;  Bs[nxt][lcol + 3][lrow] = bv0.w;
            Bs[nxt][lcol + 0][lrow + 64] = bv1.x;  Bs[nxt][lcol + 1][lrow + 64] = bv1.y;
            Bs[nxt][lcol + 2][lrow + 64] = bv1.z;  Bs[nxt][lcol + 3][lrow + 64] = bv1.w;
            __syncthreads();
        }
    }

    // epilogue: bias (+ optional ReLU)
#pragma unroll
    for (int i = 0; i < 8; i++) {
        size_t m = (size_t)(bm + tm + i);
#pragma unroll
        for (int j = 0; j < 8; j++) {
            int n = bn + tn + j;
            if (n < N) {
                float v = acc[i][j] + bias[n];
                if (RELU) v = fmaxf(v, 0.0f);
                C[m * N + n] = v;
            }
        }
    }
}

// ---------------- decoder: grouped conv (dot over DECK) + tanh -------------
__global__ void decoder_kernel(const float* __restrict__ a3,
                               const float* __restrict__ Wd,
                               const float* __restrict__ bd,
                               float* __restrict__ out)
{
    int i = blockIdx.x * blockDim.x + threadIdx.x;  // b*ADIM + a
    if (i >= BATCH * ADIM) return;
    int a = i & (ADIM - 1);
    int b = i >> 5;
    const float* dp = a3 + (size_t)b * NOUT + a * DECK;
    const float* wp = Wd + a * DECK;
    float s = bd[a];
#pragma unroll
    for (int j = 0; j < DECK; j++) s += dp[j] * wp[j];
    out[i] = tanhf(s);
}

// ---------------- launch ----------------------------------------------------
extern "C" void kernel_launch(void* const* d_in, const int* in_sizes, int n_in,
                              void* d_out, int out_size)
{
    const float* state = (const float*)d_in[0];
    const float* mean_enc = (const float*)d_in[1];
    const float* std_enc = (const float*)d_in[2];
    const float* W1 = (const float*)d_in[3];
    const float* b1 = (const float*)d_in[4];
    const float* W2 = (const float*)d_in[5];
    const float* b2 = (const float*)d_in[6];
    const float* W3 = (const float*)d_in[7];
    const float* b3 = (const float*)d_in[8];
    const float* Wd = (const float*)d_in[9];
    const float* bd = (const float*)d_in[10];
    float* out = (float*)d_out;

    void *p_spine, *p_a1, *p_a2, *p_a3;
    cudaGetSymbolAddress(&p_spine, g_spine);
    cudaGetSymbolAddress(&p_a1, g_a1);
    cudaGetSymbolAddress(&p_a2, g_a2);
    cudaGetSymbolAddress(&p_a3, g_a3);
    float* spine = (float*)p_spine;
    float* a1 = (float*)p_a1;
    float* a2 = (float*)p_a2;
    float* a3 = (float*)p_a3;

    // 1) encoder
    {
        int total = BATCH * KIN;
        int threads = 256;
        int blocks = (total + threads - 1) / threads;
        encoder_kernel<<<blocks, threads>>>(state, mean_enc, std_enc, spine);
    }
    // 2) GEMM1: a1 = relu(spine @ W1^T + b1)   [16384,1280]x[2048,1280]^T
    {
        dim3 grid(H0 / 128, BATCH / 128);
        gemm_tn<1><<<grid, 256>>>(spine, W1, b1, a1, BATCH, H0, KIN);
    }
    // 3) GEMM2: a2 = relu(a1 @ W2^T + b2)      [16384,2048]x[2048,2048]^T
    {
        dim3 grid(H1 / 128, BATCH / 128);
        gemm_tn<1><<<grid, 256>>>(a1, W2, b2, a2, BATCH, H1, H0);
    }
    // 4) GEMM3: a3 = a2 @ W3^T + b3            [16384,2048]x[320,2048]^T
    {
        dim3 grid((NOUT + 127) / 128, BATCH / 128);
        gemm_tn<0><<<grid, 256>>>(a2, W3, b3, a3, BATCH, NOUT, H1);
    }
    // 5) decoder + tanh
    {
        int total = BATCH * ADIM;
        int threads = 256;
        int blocks = (total + threads - 1) / threads;
        decoder_kernel<<<blocks, threads>>>(a3, Wd, bd, out);
    }
}

// round 4
// speedup vs baseline: 2.5265x; 2.5265x over previous
#include <cuda_runtime.h>
#include <cuda_bf16.h>
#include <stdint.h>
#include <math.h>

// ---------------- problem constants ----------------
#define BATCH  16384
#define SDIM   128
#define ENCK   10
#define KIN    1280
#define H0     2048
#define H1     2048
#define ADIM   32
#define DECK   10
#define NOUT   320

// ---------------- scratch (device globals) ----------------------------------
__device__ __nv_bfloat16 g_sp_h[(size_t)BATCH * KIN];
__device__ __nv_bfloat16 g_sp_l[(size_t)BATCH * KIN];
__device__ __nv_bfloat16 g_a1_h[(size_t)BATCH * H0];
__device__ __nv_bfloat16 g_a1_l[(size_t)BATCH * H0];
__device__ __nv_bfloat16 g_a2_h[(size_t)BATCH * H1];
__device__ __nv_bfloat16 g_a2_l[(size_t)BATCH * H1];
__device__ float         g_a3[(size_t)BATCH * NOUT];
__device__ __nv_bfloat16 g_w1_h[(size_t)H0 * KIN],  g_w1_l[(size_t)H0 * KIN];
__device__ __nv_bfloat16 g_w2_h[(size_t)H1 * H0],   g_w2_l[(size_t)H1 * H0];
__device__ __nv_bfloat16 g_w3_h[(size_t)NOUT * H1], g_w3_l[(size_t)NOUT * H1];

// ---------------- helpers ----------------------------------------------------
__device__ __forceinline__ uint32_t smem_u32(const void* p) {
    uint32_t a;
    asm("{ .reg .u64 t; cvta.to.shared.u64 t, %1; cvt.u32.u64 %0, t; }" : "=r"(a) : "l"(p));
    return a;
}
__device__ __forceinline__ void split2(float v, __nv_bfloat16& h, __nv_bfloat16& l) {
    h = __float2bfloat16(v);
    l = __float2bfloat16(v - __bfloat162float(h));
}
__device__ __forceinline__ void cp16(uint32_t dst, const void* src) {
    asm volatile("cp.async.cg.shared.global [%0], [%1], 16;" :: "r"(dst), "l"(src) : "memory");
}
__device__ __forceinline__ void cp_commit() {
    asm volatile("cp.async.commit_group;" ::: "memory");
}
__device__ __forceinline__ void ldsm4(uint32_t& r0, uint32_t& r1, uint32_t& r2, uint32_t& r3,
                                      uint32_t addr) {
    asm volatile("ldmatrix.sync.aligned.m8n8.x4.shared.b16 {%0,%1,%2,%3}, [%4];"
                 : "=r"(r0), "=r"(r1), "=r"(r2), "=r"(r3) : "r"(addr));
}
__device__ __forceinline__ void mma16816(float* c, const uint32_t* a, const uint32_t* b) {
    asm volatile("mma.sync.aligned.m16n8k16.row.col.f32.bf16.bf16.f32 "
                 "{%0,%1,%2,%3}, {%4,%5,%6,%7}, {%8,%9}, {%0,%1,%2,%3};"
                 : "+f"(c[0]), "+f"(c[1]), "+f"(c[2]), "+f"(c[3])
                 : "r"(a[0]), "r"(a[1]), "r"(a[2]), "r"(a[3]), "r"(b[0]), "r"(b[1]));
}

// ---------------- encoder ----------------------------------------------------
__global__ void encoder_kernel(const float* __restrict__ state,
                               const float* __restrict__ mean,
                               const float* __restrict__ stdv,
                               __nv_bfloat16* __restrict__ sph,
                               __nv_bfloat16* __restrict__ spl)
{
    int i = blockIdx.x * blockDim.x + threadIdx.x;
    if (i >= BATCH * KIN) return;
    int b = i / KIN;
    int k = i - b * KIN;
    int d = k / ENCK;
    float x = (state[b * SDIM + d] - mean[k]) / stdv[k];
    float v = 1.0f / (1.0f + __expf(-x));
    __nv_bfloat16 h, l;
    split2(v, h, l);
    sph[i] = h; spl[i] = l;
}

// ---------------- weight split -----------------------------------------------
__global__ void split_kernel(const float* __restrict__ w,
                             __nv_bfloat16* __restrict__ h,
                             __nv_bfloat16* __restrict__ l, int n)
{
    int i = blockIdx.x * blockDim.x + threadIdx.x;
    if (i >= n) return;
    __nv_bfloat16 hh, ll;
    split2(w[i], hh, ll);
    h[i] = hh; l[i] = ll;
}

// ---------------- mma.sync bf16 GEMM ----------------------------------------
// C[M, N_TOTAL] = A[M,K] @ W[N_TOTAL,K]^T + bias, operands given as bf16 hi/lo.
// Three tensor passes: Ah*Wh + Ah*Wl + Al*Wh (fp32 accumulate).
// BM=128, BN=128, BK=32, 256 thr (8 warps, 2m x 4n), warp tile 64x32.
// smem rows padded to 80B -> conflict-free ldmatrix.
// OUT_MODE 0: relu + split bf16 hi/lo out. OUT_MODE 1: fp32 out, ragged-N guard.
#define BK 32
#define ROWB 80                      // padded row stride in bytes (32 bf16 + 16B pad)
#define TILEB (128 * ROWB)           // 10240 B per tile
#define BUFB  (4 * TILEB)            // Ah, Al, Wh, Wl
#define SMEMB (2 * BUFB)             // double buffer = 81920

template <int N_TOTAL, int K, int OUT_MODE>
__global__ void __launch_bounds__(256)
gemm_mma(const __nv_bfloat16* __restrict__ Ah, const __nv_bfloat16* __restrict__ Al,
         const __nv_bfloat16* __restrict__ Wh, const __nv_bfloat16* __restrict__ Wl,
         const float* __restrict__ bias,
         float* __restrict__ outf,
         __nv_bfloat16* __restrict__ oh, __nv_bfloat16* __restrict__ ol)
{
    extern __shared__ __align__(16) char sm[];
    const uint32_t sb = smem_u32(sm);

    const int tid = threadIdx.x;
    const int warp = tid >> 5;
    const int lane = tid & 31;
    const int bm = blockIdx.y * 128;
    const int bn = blockIdx.x * 128;
    const int wm = (warp >> 2) * 64;      // warp m offset
    const int wn = (warp & 3) * 32;       // warp n offset

    // ---- cp.async tile staging: 4 tiles x 512 x 16B lines, 8 per thread ----
    const __nv_bfloat16* srcs[4] = {Ah, Al, Wh, Wl};
    const int NCH = K / BK;

    // per-thread (r, c) for each of the 8 lines
    int Lr[8], Lc[8], Lt[8];
    uint32_t Ldst[8];
#pragma unroll
    for (int i = 0; i < 8; i++) {
        int L = tid + (i << 8);
        Lt[i] = L >> 9;
        int rem = L & 511;
        Lr[i] = rem >> 2;
        Lc[i] = rem & 3;
        Ldst[i] = sb + Lt[i] * TILEB + Lr[i] * ROWB + Lc[i] * 16;
    }
    // gmem row per line (A rows never OOB; W rows clamped for ragged N)
    long Lrow[8];
#pragma unroll
    for (int i = 0; i < 8; i++) {
        if (Lt[i] < 2) Lrow[i] = bm + Lr[i];
        else {
            int r = bn + Lr[i];
            if (r >= N_TOTAL) r = N_TOTAL - 1;
            Lrow[i] = r;
        }
    }

    auto issue = [&](int s, int buf) {
        int k0 = s * BK;
        uint32_t boff = buf * BUFB;
#pragma unroll
        for (int i = 0; i < 8; i++) {
            const __nv_bfloat16* src = srcs[Lt[i]] + (size_t)Lrow[i] * K + k0 + Lc[i] * 8;
            cp16(Ldst[i] + boff, src);
        }
        cp_commit();
    };

    // ---- ldmatrix per-thread address components ----
    const uint32_t a_off = (uint32_t)(wm + (lane & 7) + ((lane >> 3) & 1) * 8) * ROWB
                         + (uint32_t)(((lane >> 3) >> 1) * 8) * 2;
    const uint32_t b_off = (uint32_t)(wn + ((lane >> 3) >> 1) * 8 + (lane & 7)) * ROWB
                         + (uint32_t)(((lane >> 3) & 1) * 8) * 2;

    float c[4][4][4];
#pragma unroll
    for (int mt = 0; mt < 4; mt++)
#pragma unroll
        for (int nt = 0; nt < 4; nt++)
#pragma unroll
            for (int q = 0; q < 4; q++) c[mt][nt][q] = 0.0f;

    issue(0, 0);

    for (int s = 0; s < NCH; s++) {
        if (s + 1 < NCH) {
            issue(s + 1, (s + 1) & 1);
            asm volatile("cp.async.wait_group 1;" ::: "memory");
        } else {
            asm volatile("cp.async.wait_group 0;" ::: "memory");
        }
        __syncthreads();

        const uint32_t base = sb + (s & 1) * BUFB;
        const uint32_t smAh = base, smAl = base + TILEB;
        const uint32_t smWh = base + 2 * TILEB, smWl = base + 3 * TILEB;

#pragma unroll
        for (int ks = 0; ks < 2; ks++) {
            const uint32_t kb = ks * 32;  // 16 elems * 2B
            uint32_t bh[4][2], bl[4][2];
#pragma unroll
            for (int p = 0; p < 2; p++) {
                uint32_t r0, r1, r2, r3;
                ldsm4(r0, r1, r2, r3, smWh + b_off + p * (16 * ROWB) + kb);
                bh[2 * p][0] = r0; bh[2 * p][1] = r1;
                bh[2 * p + 1][0] = r2; bh[2 * p + 1][1] = r3;
                ldsm4(r0, r1, r2, r3, smWl + b_off + p * (16 * ROWB) + kb);
                bl[2 * p][0] = r0; bl[2 * p][1] = r1;
                bl[2 * p + 1][0] = r2; bl[2 * p + 1][1] = r3;
            }
#pragma unroll
            for (int mt = 0; mt < 4; mt++) {
                uint32_t ah[4], al[4];
                ldsm4(ah[0], ah[1], ah[2], ah[3], smAh + a_off + mt * (16 * ROWB) + kb);
                ldsm4(al[0], al[1], al[2], al[3], smAl + a_off + mt * (16 * ROWB) + kb);
#pragma unroll
                for (int nt = 0; nt < 4; nt++) {
                    mma16816(c[mt][nt], ah, bh[nt]);
                    mma16816(c[mt][nt], ah, bl[nt]);
                    mma16816(c[mt][nt], al, bh[nt]);
                }
            }
        }
        __syncthreads();
    }

    // ---- epilogue ----
    const int lane4 = lane >> 2;
    const int lanem = lane & 3;
    if (OUT_MODE == 0) {
#pragma unroll
        for (int nt = 0; nt < 4; nt++) {
            int n0 = bn + wn + nt * 8 + 2 * lanem;
            float bb0 = __ldg(bias + n0), bb1 = __ldg(bias + n0 + 1);
#pragma unroll
            for (int mt = 0; mt < 4; mt++) {
                int r0 = bm + wm + mt * 16 + lane4;
                float v00 = fmaxf(c[mt][nt][0] + bb0, 0.0f);
                float v01 = fmaxf(c[mt][nt][1] + bb1, 0.0f);
                float v10 = fmaxf(c[mt][nt][2] + bb0, 0.0f);
                float v11 = fmaxf(c[mt][nt][3] + bb1, 0.0f);
                __nv_bfloat16 h0, l0, h1, l1;
                split2(v00, h0, l0); split2(v01, h1, l1);
                uint32_t hv = (uint32_t)__bfloat16_as_ushort(h0)
                            | ((uint32_t)__bfloat16_as_ushort(h1) << 16);
                uint32_t lv = (uint32_t)__bfloat16_as_ushort(l0)
                            | ((uint32_t)__bfloat16_as_ushort(l1) << 16);
                *(uint32_t*)(oh + (size_t)r0 * N_TOTAL + n0) = hv;
                *(uint32_t*)(ol + (size_t)r0 * N_TOTAL + n0) = lv;
                split2(v10, h0, l0); split2(v11, h1, l1);
                hv = (uint32_t)__bfloat16_as_ushort(h0)
                   | ((uint32_t)__bfloat16_as_ushort(h1) << 16);
                lv = (uint32_t)__bfloat16_as_ushort(l0)
                   | ((uint32_t)__bfloat16_as_ushort(l1) << 16);
                *(uint32_t*)(oh + (size_t)(r0 + 8) * N_TOTAL + n0) = hv;
                *(uint32_t*)(ol + (size_t)(r0 + 8) * N_TOTAL + n0) = lv;
            }
        }
    } else {
#pragma unroll
        for (int nt = 0; nt < 4; nt++) {
            int n0 = bn + wn + nt * 8 + 2 * lanem;
            bool ok0 = (n0 < N_TOTAL), ok1 = (n0 + 1 < N_TOTAL);
            float bb0 = ok0 ? __ldg(bias + n0) : 0.0f;
            float bb1 = ok1 ? __ldg(bias + n0 + 1) : 0.0f;
#pragma unroll
            for (int mt = 0; mt < 4; mt++) {
                int r0 = bm + wm + mt * 16 + lane4;
                if (ok0) {
                    outf[(size_t)r0 * N_TOTAL + n0] = c[mt][nt][0] + bb0;
                    outf[(size_t)(r0 + 8) * N_TOTAL + n0] = c[mt][nt][2] + bb0;
                }
                if (ok1) {
                    outf[(size_t)r0 * N_TOTAL + n0 + 1] = c[mt][nt][1] + bb1;
                    outf[(size_t)(r0 + 8) * N_TOTAL + n0 + 1] = c[mt][nt][3] + bb1;
                }
            }
        }
    }
}

// ---------------- decoder ----------------------------------------------------
__global__ void decoder_kernel(const float* __restrict__ a3,
                               const float* __restrict__ Wd,
                               const float* __restrict__ bd,
                               float* __restrict__ out)
{
    int i = blockIdx.x * blockDim.x + threadIdx.x;
    if (i >= BATCH * ADIM) return;
    int a = i & (ADIM - 1);
    int b = i >> 5;
    const float* dp = a3 + (size_t)b * NOUT + a * DECK;
    const float* wp = Wd + a * DECK;
    float s = bd[a];
#pragma unroll
    for (int j = 0; j < DECK; j++) s += dp[j] * wp[j];
    out[i] = tanhf(s);
}

// ---------------- launch -----------------------------------------------------
extern "C" void kernel_launch(void* const* d_in, const int* in_sizes, int n_in,
                              void* d_out, int out_size)
{
    const float* state = (const float*)d_in[0];
    const float* mean_enc = (const float*)d_in[1];
    const float* std_enc = (const float*)d_in[2];
    const float* W1 = (const float*)d_in[3];
    const float* b1 = (const float*)d_in[4];
    const float* W2 = (const float*)d_in[5];
    const float* b2 = (const float*)d_in[6];
    const float* W3 = (const float*)d_in[7];
    const float* b3 = (const float*)d_in[8];
    const float* Wd = (const float*)d_in[9];
    const float* bd = (const float*)d_in[10];
    float* out = (float*)d_out;

    void *sp_h, *sp_l, *a1_h, *a1_l, *a2_h, *a2_l, *a3;
    void *w1h, *w1l, *w2h, *w2l, *w3h, *w3l;
    cudaGetSymbolAddress(&sp_h, g_sp_h);  cudaGetSymbolAddress(&sp_l, g_sp_l);
    cudaGetSymbolAddress(&a1_h, g_a1_h);  cudaGetSymbolAddress(&a1_l, g_a1_l);
    cudaGetSymbolAddress(&a2_h, g_a2_h);  cudaGetSymbolAddress(&a2_l, g_a2_l);
    cudaGetSymbolAddress(&a3, g_a3);
    cudaGetSymbolAddress(&w1h, g_w1_h);   cudaGetSymbolAddress(&w1l, g_w1_l);
    cudaGetSymbolAddress(&w2h, g_w2_h);   cudaGetSymbolAddress(&w2l, g_w2_l);
    cudaGetSymbolAddress(&w3h, g_w3_h);   cudaGetSymbolAddress(&w3l, g_w3_l);

    cudaFuncSetAttribute(gemm_mma<H0, KIN, 0>, cudaFuncAttributeMaxDynamicSharedMemorySize, SMEMB);
    cudaFuncSetAttribute(gemm_mma<H1, H0, 0>, cudaFuncAttributeMaxDynamicSharedMemorySize, SMEMB);
    cudaFuncSetAttribute(gemm_mma<NOUT, H1, 1>, cudaFuncAttributeMaxDynamicSharedMemorySize, SMEMB);

    // weight splits
    {
        int n1 = H0 * KIN, n2 = H1 * H0, n3 = NOUT * H1;
        split_kernel<<<(n1 + 255) / 256, 256>>>(W1, (__nv_bfloat16*)w1h, (__nv_bfloat16*)w1l, n1);
        split_kernel<<<(n2 + 255) / 256, 256>>>(W2, (__nv_bfloat16*)w2h, (__nv_bfloat16*)w2l, n2);
        split_kernel<<<(n3 + 255) / 256, 256>>>(W3, (__nv_bfloat16*)w3h, (__nv_bfloat16*)w3l, n3);
    }
    // encoder
    {
        int total = BATCH * KIN;
        encoder_kernel<<<(total + 255) / 256, 256>>>(state, mean_enc, std_enc,
                                                     (__nv_bfloat16*)sp_h, (__nv_bfloat16*)sp_l);
    }
    // GEMM1: spine -> a1 (relu, split out)
    {
        dim3 grid(H0 / 128, BATCH / 128);
        gemm_mma<H0, KIN, 0><<<grid, 256, SMEMB>>>(
            (const __nv_bfloat16*)sp_h, (const __nv_bfloat16*)sp_l,
            (const __nv_bfloat16*)w1h, (const __nv_bfloat16*)w1l,
            b1, nullptr, (__nv_bfloat16*)a1_h, (__nv_bfloat16*)a1_l);
    }
    // GEMM2: a1 -> a2 (relu, split out)
    {
        dim3 grid(H1 / 128, BATCH / 128);
        gemm_mma<H1, H0, 0><<<grid, 256, SMEMB>>>(
            (const __nv_bfloat16*)a1_h, (const __nv_bfloat16*)a1_l,
            (const __nv_bfloat16*)w2h, (const __nv_bfloat16*)w2l,
            b2, nullptr, (__nv_bfloat16*)a2_h, (__nv_bfloat16*)a2_l);
    }
    // GEMM3: a2 -> a3 (fp32 out, ragged N)
    {
        dim3 grid((NOUT + 127) / 128, BATCH / 128);
        gemm_mma<NOUT, H1, 1><<<grid, 256, SMEMB>>>(
            (const __nv_bfloat16*)a2_h, (const __nv_bfloat16*)a2_l,
            (const __nv_bfloat16*)w3h, (const __nv_bfloat16*)w3l,
            b3, (float*)a3, nullptr, nullptr);
    }
    // decoder
    {
        int total = BATCH * ADIM;
        decoder_kernel<<<(total + 255) / 256, 256>>>((const float*)a3, Wd, bd, out);
    }
}

// round 5
// speedup vs baseline: 3.7745x; 1.4940x over previous
#include <cuda_runtime.h>
#include <cuda_fp16.h>
#include <stdint.h>
#include <math.h>

// ---------------- problem constants ----------------
#define BATCH  16384
#define SDIM   128
#define ENCK   10
#define KIN    1280
#define H0     2048
#define H1     2048
#define ADIM   32
#define DECK   10
#define NOUT   320

// ---------------- scratch (device globals) ----------------------------------
__device__ __half g_sp_h[(size_t)BATCH * KIN];
__device__ __half g_sp_l[(size_t)BATCH * KIN];
__device__ __half g_a1_h[(size_t)BATCH * H0];
__device__ __half g_a1_l[(size_t)BATCH * H0];
__device__ __half g_a2_h[(size_t)BATCH * H1];
__device__ __half g_a2_l[(size_t)BATCH * H1];
__device__ float  g_a3[(size_t)BATCH * NOUT];
__device__ __half g_w1[(size_t)H0 * KIN];
__device__ __half g_w2[(size_t)H1 * H0];
__device__ __half g_w3[(size_t)NOUT * H1];

// ---------------- helpers ----------------------------------------------------
__device__ __forceinline__ uint32_t smem_u32(const void* p) {
    uint32_t a;
    asm("{ .reg .u64 t; cvta.to.shared.u64 t, %1; cvt.u32.u64 %0, t; }" : "=r"(a) : "l"(p));
    return a;
}
__device__ __forceinline__ void split2h(float v, __half& h, __half& l) {
    h = __float2half_rn(v);
    l = __float2half_rn(v - __half2float(h));
}
__device__ __forceinline__ void cp16(uint32_t dst, const void* src) {
    asm volatile("cp.async.cg.shared.global [%0], [%1], 16;" :: "r"(dst), "l"(src) : "memory");
}
__device__ __forceinline__ void cp_commit() {
    asm volatile("cp.async.commit_group;" ::: "memory");
}
__device__ __forceinline__ void ldsm4(uint32_t& r0, uint32_t& r1, uint32_t& r2, uint32_t& r3,
                                      uint32_t addr) {
    asm volatile("ldmatrix.sync.aligned.m8n8.x4.shared.b16 {%0,%1,%2,%3}, [%4];"
                 : "=r"(r0), "=r"(r1), "=r"(r2), "=r"(r3) : "r"(addr));
}
__device__ __forceinline__ void mma16816(float* c, const uint32_t* a, const uint32_t* b) {
    asm volatile("mma.sync.aligned.m16n8k16.row.col.f32.f16.f16.f32 "
                 "{%0,%1,%2,%3}, {%4,%5,%6,%7}, {%8,%9}, {%0,%1,%2,%3};"
                 : "+f"(c[0]), "+f"(c[1]), "+f"(c[2]), "+f"(c[3])
                 : "r"(a[0]), "r"(a[1]), "r"(a[2]), "r"(a[3]), "r"(b[0]), "r"(b[1]));
}

// ---------------- encoder ----------------------------------------------------
__global__ void encoder_kernel(const float* __restrict__ state,
                               const float* __restrict__ mean,
                               const float* __restrict__ stdv,
                               __half* __restrict__ sph,
                               __half* __restrict__ spl)
{
    int i = blockIdx.x * blockDim.x + threadIdx.x;
    if (i >= BATCH * KIN) return;
    int b = i / KIN;
    int k = i - b * KIN;
    int d = k / ENCK;
    float x = (state[b * SDIM + d] - mean[k]) / stdv[k];
    float v = 1.0f / (1.0f + __expf(-x));
    __half h, l;
    split2h(v, h, l);
    sph[i] = h; spl[i] = l;
}

// ---------------- weight convert (fp32 -> fp16) ------------------------------
__global__ void convert_kernel(const float* __restrict__ w,
                               __half* __restrict__ o, int n)
{
    int i = blockIdx.x * blockDim.x + threadIdx.x;
    if (i >= n) return;
    o[i] = __float2half_rn(w[i]);
}

// ---------------- mma.sync fp16 GEMM -----------------------------------------
// C[M, N_TOTAL] = A[M,K] @ W[N_TOTAL,K]^T + bias, A = Ah + Al (fp16 pair), W fp16.
// Two tensor passes into same fp32 accumulator: Ah*W + Al*W.
// BM=128, BN=128, BK=32, 256 thr (8 warps, 2m x 4n), warp tile 64x32.
// 3-stage cp.async pipeline; smem rows padded to 80B -> conflict-free ldmatrix.
// OUT_MODE 0: relu + split fp16 hi/lo out. OUT_MODE 1: fp32 out, ragged-N guard.
#define BK 32
#define ROWB 80                       // padded row stride in bytes
#define TILEB (128 * ROWB)            // 10240 B per tile
#define STAGEB (3 * TILEB)            // Ah, Al, W = 30720 B
#define NSTAGE 3
#define SMEMB (NSTAGE * STAGEB)       // 92160 B

template <int N_TOTAL, int K, int OUT_MODE>
__global__ void __launch_bounds__(256, 2)
gemm_mma(const __half* __restrict__ Ah, const __half* __restrict__ Al,
         const __half* __restrict__ W,
         const float* __restrict__ bias,
         float* __restrict__ outf,
         __half* __restrict__ oh, __half* __restrict__ ol)
{
    extern __shared__ __align__(16) char sm[];
    const uint32_t sb = smem_u32(sm);

    const int tid = threadIdx.x;
    const int warp = tid >> 5;
    const int lane = tid & 31;
    const int bm = blockIdx.y * 128;
    const int bn = blockIdx.x * 128;
    const int wm = (warp >> 2) * 64;
    const int wn = (warp & 3) * 32;

    const __half* srcs[3] = {Ah, Al, W};
    const int NCH = K / BK;

    // per-thread staging lines: 3 tiles x 512 lines (128 rows x 4 x 16B), 6/thread
    int Lt[6], Lr[6], Lc[6];
    uint32_t Ldst[6];
    long Lrow[6];
#pragma unroll
    for (int i = 0; i < 6; i++) {
        int L = tid + (i << 8);
        Lt[i] = L >> 9;
        int rem = L & 511;
        Lr[i] = rem >> 2;
        Lc[i] = rem & 3;
        Ldst[i] = sb + Lt[i] * TILEB + Lr[i] * ROWB + Lc[i] * 16;
        if (Lt[i] < 2) Lrow[i] = bm + Lr[i];
        else {
            int r = bn + Lr[i];
            if (r >= N_TOTAL) r = N_TOTAL - 1;
            Lrow[i] = r;
        }
    }

    auto issue = [&](int s) {
        int k0 = s * BK;
        uint32_t boff = (s % NSTAGE) * STAGEB;
#pragma unroll
        for (int i = 0; i < 6; i++) {
            const __half* src = srcs[Lt[i]] + (size_t)Lrow[i] * K + k0 + Lc[i] * 8;
            cp16(Ldst[i] + boff, src);
        }
        cp_commit();
    };

    // ldmatrix per-thread address components (row.col layout, as validated)
    const uint32_t a_off = (uint32_t)(wm + (lane & 7) + ((lane >> 3) & 1) * 8) * ROWB
                         + (uint32_t)(((lane >> 3) >> 1) * 8) * 2;
    const uint32_t b_off = (uint32_t)(wn + ((lane >> 3) >> 1) * 8 + (lane & 7)) * ROWB
                         + (uint32_t)(((lane >> 3) & 1) * 8) * 2;

    float c[4][4][4];
#pragma unroll
    for (int mt = 0; mt < 4; mt++)
#pragma unroll
        for (int nt = 0; nt < 4; nt++)
#pragma unroll
            for (int q = 0; q < 4; q++) c[mt][nt][q] = 0.0f;

    issue(0);
    if (NCH > 1) issue(1);

    for (int s = 0; s < NCH; s++) {
        if (s + 2 < NCH) {
            issue(s + 2);
            asm volatile("cp.async.wait_group 2;" ::: "memory");
        } else if (s + 1 < NCH) {
            asm volatile("cp.async.wait_group 1;" ::: "memory");
        } else {
            asm volatile("cp.async.wait_group 0;" ::: "memory");
        }
        __syncthreads();

        const uint32_t base = sb + (s % NSTAGE) * STAGEB;
        const uint32_t smAh = base, smAl = base + TILEB, smW = base + 2 * TILEB;

#pragma unroll
        for (int ks = 0; ks < 2; ks++) {
            const uint32_t kb = ks * 32;
            uint32_t bw[4][2];
#pragma unroll
            for (int p = 0; p < 2; p++) {
                uint32_t r0, r1, r2, r3;
                ldsm4(r0, r1, r2, r3, smW + b_off + p * (16 * ROWB) + kb);
                bw[2 * p][0] = r0; bw[2 * p][1] = r1;
                bw[2 * p + 1][0] = r2; bw[2 * p + 1][1] = r3;
            }
#pragma unroll
            for (int mt = 0; mt < 4; mt++) {
                uint32_t ah[4], al[4];
                ldsm4(ah[0], ah[1], ah[2], ah[3], smAh + a_off + mt * (16 * ROWB) + kb);
                ldsm4(al[0], al[1], al[2], al[3], smAl + a_off + mt * (16 * ROWB) + kb);
#pragma unroll
                for (int nt = 0; nt < 4; nt++) {
                    mma16816(c[mt][nt], ah, bw[nt]);
                    mma16816(c[mt][nt], al, bw[nt]);
                }
            }
        }
        __syncthreads();
    }

    // ---- epilogue ----
    const int lane4 = lane >> 2;
    const int lanem = lane & 3;
    if (OUT_MODE == 0) {
#pragma unroll
        for (int nt = 0; nt < 4; nt++) {
            int n0 = bn + wn + nt * 8 + 2 * lanem;
            float bb0 = __ldg(bias + n0), bb1 = __ldg(bias + n0 + 1);
#pragma unroll
            for (int mt = 0; mt < 4; mt++) {
                int r0 = bm + wm + mt * 16 + lane4;
                float v00 = fmaxf(c[mt][nt][0] + bb0, 0.0f);
                float v01 = fmaxf(c[mt][nt][1] + bb1, 0.0f);
                float v10 = fmaxf(c[mt][nt][2] + bb0, 0.0f);
                float v11 = fmaxf(c[mt][nt][3] + bb1, 0.0f);
                __half h0, l0, h1, l1;
                split2h(v00, h0, l0); split2h(v01, h1, l1);
                uint32_t hv = (uint32_t)__half_as_ushort(h0)
                            | ((uint32_t)__half_as_ushort(h1) << 16);
                uint32_t lv = (uint32_t)__half_as_ushort(l0)
                            | ((uint32_t)__half_as_ushort(l1) << 16);
                *(uint32_t*)(oh + (size_t)r0 * N_TOTAL + n0) = hv;
                *(uint32_t*)(ol + (size_t)r0 * N_TOTAL + n0) = lv;
                split2h(v10, h0, l0); split2h(v11, h1, l1);
                hv = (uint32_t)__half_as_ushort(h0)
                   | ((uint32_t)__half_as_ushort(h1) << 16);
                lv = (uint32_t)__half_as_ushort(l0)
                   | ((uint32_t)__half_as_ushort(l1) << 16);
                *(uint32_t*)(oh + (size_t)(r0 + 8) * N_TOTAL + n0) = hv;
                *(uint32_t*)(ol + (size_t)(r0 + 8) * N_TOTAL + n0) = lv;
            }
        }
    } else {
#pragma unroll
        for (int nt = 0; nt < 4; nt++) {
            int n0 = bn + wn + nt * 8 + 2 * lanem;
            bool ok0 = (n0 < N_TOTAL), ok1 = (n0 + 1 < N_TOTAL);
            float bb0 = ok0 ? __ldg(bias + n0) : 0.0f;
            float bb1 = ok1 ? __ldg(bias + n0 + 1) : 0.0f;
#pragma unroll
            for (int mt = 0; mt < 4; mt++) {
                int r0 = bm + wm + mt * 16 + lane4;
                if (ok0) {
                    outf[(size_t)r0 * N_TOTAL + n0] = c[mt][nt][0] + bb0;
                    outf[(size_t)(r0 + 8) * N_TOTAL + n0] = c[mt][nt][2] + bb0;
                }
                if (ok1) {
                    outf[(size_t)r0 * N_TOTAL + n0 + 1] = c[mt][nt][1] + bb1;
                    outf[(size_t)(r0 + 8) * N_TOTAL + n0 + 1] = c[mt][nt][3] + bb1;
                }
            }
        }
    }
}

// ---------------- decoder ----------------------------------------------------
__global__ void decoder_kernel(const float* __restrict__ a3,
                               const float* __restrict__ Wd,
                               const float* __restrict__ bd,
                               float* __restrict__ out)
{
    int i = blockIdx.x * blockDim.x + threadIdx.x;
    if (i >= BATCH * ADIM) return;
    int a = i & (ADIM - 1);
    int b = i >> 5;
    const float* dp = a3 + (size_t)b * NOUT + a * DECK;
    const float* wp = Wd + a * DECK;
    float s = bd[a];
#pragma unroll
    for (int j = 0; j < DECK; j++) s += dp[j] * wp[j];
    out[i] = tanhf(s);
}

// ---------------- launch -----------------------------------------------------
extern "C" void kernel_launch(void* const* d_in, const int* in_sizes, int n_in,
                              void* d_out, int out_size)
{
    const float* state = (const float*)d_in[0];
    const float* mean_enc = (const float*)d_in[1];
    const float* std_enc = (const float*)d_in[2];
    const float* W1 = (const float*)d_in[3];
    const float* b1 = (const float*)d_in[4];
    const float* W2 = (const float*)d_in[5];
    const float* b2 = (const float*)d_in[6];
    const float* W3 = (const float*)d_in[7];
    const float* b3 = (const float*)d_in[8];
    const float* Wd = (const float*)d_in[9];
    const float* bd = (const float*)d_in[10];
    float* out = (float*)d_out;

    void *sp_h, *sp_l, *a1_h, *a1_l, *a2_h, *a2_l, *a3;
    void *w1, *w2, *w3;
    cudaGetSymbolAddress(&sp_h, g_sp_h);  cudaGetSymbolAddress(&sp_l, g_sp_l);
    cudaGetSymbolAddress(&a1_h, g_a1_h);  cudaGetSymbolAddress(&a1_l, g_a1_l);
    cudaGetSymbolAddress(&a2_h, g_a2_h);  cudaGetSymbolAddress(&a2_l, g_a2_l);
    cudaGetSymbolAddress(&a3, g_a3);
    cudaGetSymbolAddress(&w1, g_w1);
    cudaGetSymbolAddress(&w2, g_w2);
    cudaGetSymbolAddress(&w3, g_w3);

    cudaFuncSetAttribute(gemm_mma<H0, KIN, 0>, cudaFuncAttributeMaxDynamicSharedMemorySize, SMEMB);
    cudaFuncSetAttribute(gemm_mma<H1, H0, 0>, cudaFuncAttributeMaxDynamicSharedMemorySize, SMEMB);
    cudaFuncSetAttribute(gemm_mma<NOUT, H1, 1>, cudaFuncAttributeMaxDynamicSharedMemorySize, SMEMB);

    // weight converts
    {
        int n1 = H0 * KIN, n2 = H1 * H0, n3 = NOUT * H1;
        convert_kernel<<<(n1 + 255) / 256, 256>>>(W1, (__half*)w1, n1);
        convert_kernel<<<(n2 + 255) / 256, 256>>>(W2, (__half*)w2, n2);
        convert_kernel<<<(n3 + 255) / 256, 256>>>(W3, (__half*)w3, n3);
    }
    // encoder
    {
        int total = BATCH * KIN;
        encoder_kernel<<<(total + 255) / 256, 256>>>(state, mean_enc, std_enc,
                                                     (__half*)sp_h, (__half*)sp_l);
    }
    // GEMM1
    {
        dim3 grid(H0 / 128, BATCH / 128);
        gemm_mma<H0, KIN, 0><<<grid, 256, SMEMB>>>(
            (const __half*)sp_h, (const __half*)sp_l, (const __half*)w1,
            b1, nullptr, (__half*)a1_h, (__half*)a1_l);
    }
    // GEMM2
    {
        dim3 grid(H1 / 128, BATCH / 128);
        gemm_mma<H1, H0, 0><<<grid, 256, SMEMB>>>(
            (const __half*)a1_h, (const __half*)a1_l, (const __half*)w2,
            b2, nullptr, (__half*)a2_h, (__half*)a2_l);
    }
    // GEMM3 (fp32 out, ragged N)
    {
        dim3 grid((NOUT + 127) / 128, BATCH / 128);
        gemm_mma<NOUT, H1, 1><<<grid, 256, SMEMB>>>(
            (const __half*)a2_h, (const __half*)a2_l, (const __half*)w3,
            b3, (float*)a3, nullptr, nullptr);
    }
    // decoder
    {
        int total = BATCH * ADIM;
        decoder_kernel<<<(total + 255) / 256, 256>>>((const float*)a3, Wd, bd, out);
    }
}